// round 3
// baseline (speedup 1.0000x reference)
#include <cuda_runtime.h>
#include <math.h>

#define B 2048
#define N 128
#define D 512
#define BD (B * D)
#define NW 12            // warps per CTA in fuse kernel
#define NT (NW * 32)     // 384 threads

// 8 MB scratch for cw = content @ cow, rows interleaved: row 2b = text[b]@cow, 2b+1 = img[b]@cow
__device__ float g_cw[2 * B * D];

__device__ __forceinline__ float tanha(float x) {
    float y;
    asm("tanh.approx.f32 %0, %1;" : "=f"(y) : "f"(x));
    return y;
}
__device__ __forceinline__ float ex2(float x) {
    float y;
    asm("ex2.approx.f32 %0, %1;" : "=f"(y) : "f"(x));
    return y;
}

// ---------------------------------------------------------------------------
// Kernel 1: cw[4096, 512] = A[4096, 512] @ cow[512, 512]  (fp32, near FFMA floor)
// ---------------------------------------------------------------------------
__global__ __launch_bounds__(256) void gemm_cw_kernel(
    const float* __restrict__ text,
    const float* __restrict__ img,
    const float* __restrict__ cow)
{
    __shared__ float As[16][64];
    __shared__ float Bs[16][64];

    const int tx = threadIdx.x;
    const int block_row = blockIdx.y * 64;
    const int block_col = blockIdx.x * 64;
    const int tr = (tx / 16) * 4;
    const int tc = (tx % 16) * 4;

    float acc[4][4];
#pragma unroll
    for (int i = 0; i < 4; i++)
#pragma unroll
        for (int j = 0; j < 4; j++) acc[i][j] = 0.f;

    for (int k0 = 0; k0 < D; k0 += 16) {
        {
            int m = tx >> 2;
            int kk = (tx & 3) * 4;
            int r = block_row + m;
            const float* Ap = ((r & 1) ? img : text) + (size_t)(r >> 1) * D + k0 + kk;
            float4 v = *reinterpret_cast<const float4*>(Ap);
            As[kk + 0][m] = v.x;
            As[kk + 1][m] = v.y;
            As[kk + 2][m] = v.z;
            As[kk + 3][m] = v.w;
        }
        {
            int kk = tx >> 4;
            int c = (tx & 15) * 4;
            float4 v = *reinterpret_cast<const float4*>(cow + (size_t)(k0 + kk) * D + block_col + c);
            *reinterpret_cast<float4*>(&Bs[kk][c]) = v;
        }
        __syncthreads();
#pragma unroll
        for (int k = 0; k < 16; k++) {
            float4 a4 = *reinterpret_cast<const float4*>(&As[k][tr]);
            float4 b4 = *reinterpret_cast<const float4*>(&Bs[k][tc]);
            float a[4] = {a4.x, a4.y, a4.z, a4.w};
            float b[4] = {b4.x, b4.y, b4.z, b4.w};
#pragma unroll
            for (int i = 0; i < 4; i++)
#pragma unroll
                for (int j = 0; j < 4; j++) acc[i][j] = fmaf(a[i], b[j], acc[i][j]);
        }
        __syncthreads();
    }

#pragma unroll
    for (int i = 0; i < 4; i++) {
        float4 v = make_float4(acc[i][0], acc[i][1], acc[i][2], acc[i][3]);
        *reinterpret_cast<float4*>(&g_cw[(size_t)(block_row + tr + i) * D + block_col + tc]) = v;
    }
}

// ---------------------------------------------------------------------------
// Kernel 2: one CTA (12 warps) per sample. Warp w owns rows n = w, w+NW, ...
// Branchless UNSHIFTED softmax (|logit| <= ||W_co||_1 ~ 18, exp fits fp32):
// only loop-carried dependency is a pipelined FMA accumulate.
// Depth-2 double-buffered z prefetch, unroll-by-2 (no register copies).
// ---------------------------------------------------------------------------
__global__ __launch_bounds__(NT, 1) void fuse_kernel(
    const float* __restrict__ text,
    const float* __restrict__ img,
    const float* __restrict__ comment,
    const int*   __restrict__ comment_num,
    const float* __restrict__ W_ca,
    const float* __restrict__ W_co,
    float* __restrict__ out)
{
    const int b = blockIdx.x;
    const int tid = threadIdx.x;
    const int w = tid >> 5;
    const int lane = tid & 31;

    __shared__ float s_cw0[D], s_cw1[D], s_c0[D], s_c1[D];
    __shared__ float s_accA0[D], s_accA1[D];
    __shared__ float s_buf[NW][D];
    __shared__ float s_s[NW];
    __shared__ float s_w01[2];

    for (int d = tid; d < D; d += NT) {
        s_cw0[d] = g_cw[(size_t)(2 * b) * D + d];
        s_cw1[d] = g_cw[(size_t)(2 * b + 1) * D + d];
        s_c0[d]  = text[(size_t)b * D + d];
        s_c1[d]  = img[(size_t)b * D + d];
        s_accA0[d] = 0.f;
        s_accA1[d] = 0.f;
    }
    __syncthreads();

    // Hoist loop-invariant per-thread slices into registers.
    const float LOG2E = 1.4426950408889634f;
    float4 c0r[4], c1r[4], wr[4];
#pragma unroll
    for (int j = 0; j < 4; j++) {
        int q = lane + 32 * j;
        c0r[j] = reinterpret_cast<const float4*>(s_c0)[q];
        c1r[j] = reinterpret_cast<const float4*>(s_c1)[q];
        float4 wv = __ldg(&reinterpret_cast<const float4*>(W_co)[q]);
        wr[j] = make_float4(wv.x * LOG2E, wv.y * LOG2E, wv.z * LOG2E, wv.w * LOG2E);
    }

    const int num = comment_num[b];
    const float4* zbase = reinterpret_cast<const float4*>(comment + (size_t)b * N * D);

    float4 aA0[4], aA1[4], aC[4];
#pragma unroll
    for (int j = 0; j < 4; j++) {
        aA0[j] = make_float4(0.f, 0.f, 0.f, 0.f);
        aA1[j] = make_float4(0.f, 0.f, 0.f, 0.f);
        aC[j]  = make_float4(0.f, 0.f, 0.f, 0.f);
    }
    float ssum = 0.f;

    // Double-buffered prefetch: A holds row n, Bv holds row n+NW.
    float4 Az[4], Bz[4];
    if (w < num) {
        const float4* zr = zbase + (size_t)w * (D / 4);
#pragma unroll
        for (int j = 0; j < 4; j++) Az[j] = __ldg(&zr[lane + 32 * j]);
    }
    if (w + NW < num) {
        const float4* zr = zbase + (size_t)(w + NW) * (D / 4);
#pragma unroll
        for (int j = 0; j < 4; j++) Bz[j] = __ldg(&zr[lane + 32 * j]);
    }

#define PROCESS(ZBUF)                                                              \
    {                                                                              \
        float d0 = 0.f, d1 = 0.f;                                                  \
        _Pragma("unroll")                                                          \
        for (int j = 0; j < 4; j++) {                                              \
            int q = lane + 32 * j;                                                 \
            float4 a = reinterpret_cast<const float4*>(s_cw0)[q];                  \
            float4 c = reinterpret_cast<const float4*>(s_cw1)[q];                  \
            d0 = fmaf(ZBUF[j].x, a.x, fmaf(ZBUF[j].y, a.y,                         \
                 fmaf(ZBUF[j].z, a.z, fmaf(ZBUF[j].w, a.w, d0))));                 \
            d1 = fmaf(ZBUF[j].x, c.x, fmaf(ZBUF[j].y, c.y,                         \
                 fmaf(ZBUF[j].z, c.z, fmaf(ZBUF[j].w, c.w, d1))));                 \
        }                                                                          \
        _Pragma("unroll")                                                          \
        for (int off = 16; off; off >>= 1) {                                       \
            d0 += __shfl_xor_sync(0xffffffffu, d0, off);                           \
            d1 += __shfl_xor_sync(0xffffffffu, d1, off);                           \
        }                                                                          \
        float t0 = tanha(d0);                                                      \
        float t1 = tanha(d1);                                                      \
        float lp = 0.f;                                                            \
        _Pragma("unroll")                                                          \
        for (int j = 0; j < 4; j++) {                                              \
            float zt;                                                              \
            zt = tanha(fmaf(t0, c0r[j].x, fmaf(t1, c1r[j].x, ZBUF[j].x)));         \
            lp = fmaf(zt, wr[j].x, lp);                                            \
            zt = tanha(fmaf(t0, c0r[j].y, fmaf(t1, c1r[j].y, ZBUF[j].y)));         \
            lp = fmaf(zt, wr[j].y, lp);                                            \
            zt = tanha(fmaf(t0, c0r[j].z, fmaf(t1, c1r[j].z, ZBUF[j].z)));         \
            lp = fmaf(zt, wr[j].z, lp);                                            \
            zt = tanha(fmaf(t0, c0r[j].w, fmaf(t1, c1r[j].w, ZBUF[j].w)));         \
            lp = fmaf(zt, wr[j].w, lp);                                            \
            aA0[j].x = fmaf(t0, ZBUF[j].x, aA0[j].x);                              \
            aA0[j].y = fmaf(t0, ZBUF[j].y, aA0[j].y);                              \
            aA0[j].z = fmaf(t0, ZBUF[j].z, aA0[j].z);                              \
            aA0[j].w = fmaf(t0, ZBUF[j].w, aA0[j].w);                              \
            aA1[j].x = fmaf(t1, ZBUF[j].x, aA1[j].x);                              \
            aA1[j].y = fmaf(t1, ZBUF[j].y, aA1[j].y);                              \
            aA1[j].z = fmaf(t1, ZBUF[j].z, aA1[j].z);                              \
            aA1[j].w = fmaf(t1, ZBUF[j].w, aA1[j].w);                              \
        }                                                                          \
        _Pragma("unroll")                                                          \
        for (int off = 16; off; off >>= 1)                                         \
            lp += __shfl_xor_sync(0xffffffffu, lp, off);                           \
        float e = ex2(lp);                                                         \
        ssum += e;                                                                 \
        _Pragma("unroll")                                                          \
        for (int j = 0; j < 4; j++) {                                              \
            aC[j].x = fmaf(e, ZBUF[j].x, aC[j].x);                                 \
            aC[j].y = fmaf(e, ZBUF[j].y, aC[j].y);                                 \
            aC[j].z = fmaf(e, ZBUF[j].z, aC[j].z);                                 \
            aC[j].w = fmaf(e, ZBUF[j].w, aC[j].w);                                 \
        }                                                                          \
    }

    for (int n = w; n < num; n += 2 * NW) {
        PROCESS(Az);
        if (n + 2 * NW < num) {
            const float4* zr = zbase + (size_t)(n + 2 * NW) * (D / 4);
#pragma unroll
            for (int j = 0; j < 4; j++) Az[j] = __ldg(&zr[lane + 32 * j]);
        }
        if (n + NW < num) {
            PROCESS(Bz);
            if (n + 3 * NW < num) {
                const float4* zr = zbase + (size_t)(n + 3 * NW) * (D / 4);
#pragma unroll
                for (int j = 0; j < 4; j++) Bz[j] = __ldg(&zr[lane + 32 * j]);
            }
        }
    }
#undef PROCESS

    // stash warp state
    if (lane == 0) s_s[w] = ssum;
#pragma unroll
    for (int j = 0; j < 4; j++) {
        int base = (lane + 32 * j) * 4;
        *reinterpret_cast<float4*>(&s_buf[w][base]) = aC[j];
        atomicAdd(&s_accA0[base + 0], aA0[j].x);
        atomicAdd(&s_accA0[base + 1], aA0[j].y);
        atomicAdd(&s_accA0[base + 2], aA0[j].z);
        atomicAdd(&s_accA0[base + 3], aA0[j].w);
        atomicAdd(&s_accA1[base + 0], aA1[j].x);
        atomicAdd(&s_accA1[base + 1], aA1[j].y);
        atomicAdd(&s_accA1[base + 2], aA1[j].z);
        atomicAdd(&s_accA1[base + 3], aA1[j].w);
    }
    __syncthreads();

    // refine_comment[d] = sum_w acc_w[d] / sum_w s_w   (unshifted softmax)
    {
        float S = 0.f;
#pragma unroll
        for (int i = 0; i < NW; i++) S += s_s[i];
        float invS = __frcp_rn(S);
        for (int d = tid; d < D; d += NT) {
            float rc = 0.f;
#pragma unroll
            for (int i = 0; i < NW; i++) rc = fmaf(s_buf[i][d], invS, rc) ;
            out[BD + (size_t)b * D + d] = rc;
        }
    }

    // content attention logits (warp 0 covers all 512 d via its 16-slice)
    if (w == 0) {
        float v0 = 0.f, v1 = 0.f;
#pragma unroll
        for (int j = 0; j < 4; j++) {
            int base = (lane + 32 * j) * 4;
            float4 wa = __ldg(&reinterpret_cast<const float4*>(W_ca)[lane + 32 * j]);
            v0 = fmaf(tanha(c0r[j].x + s_accA0[base + 0]), wa.x, v0);
            v0 = fmaf(tanha(c0r[j].y + s_accA0[base + 1]), wa.y, v0);
            v0 = fmaf(tanha(c0r[j].z + s_accA0[base + 2]), wa.z, v0);
            v0 = fmaf(tanha(c0r[j].w + s_accA0[base + 3]), wa.w, v0);
            v1 = fmaf(tanha(c1r[j].x + s_accA1[base + 0]), wa.x, v1);
            v1 = fmaf(tanha(c1r[j].y + s_accA1[base + 1]), wa.y, v1);
            v1 = fmaf(tanha(c1r[j].z + s_accA1[base + 2]), wa.z, v1);
            v1 = fmaf(tanha(c1r[j].w + s_accA1[base + 3]), wa.w, v1);
        }
#pragma unroll
        for (int off = 16; off; off >>= 1) {
            v0 += __shfl_xor_sync(0xffffffffu, v0, off);
            v1 += __shfl_xor_sync(0xffffffffu, v1, off);
        }
        if (lane == 0) {
            float mm = fmaxf(v0, v1);
            float e0 = __expf(v0 - mm), e1 = __expf(v1 - mm);
            float inv = __frcp_rn(e0 + e1);
            float w0 = e0 * inv, w1 = e1 * inv;
            s_w01[0] = w0; s_w01[1] = w1;
            out[2 * BD + 2 * b + 0] = w0;
            out[2 * BD + 2 * b + 1] = w1;
        }
    }
    __syncthreads();

    {
        float w0 = s_w01[0], w1 = s_w01[1];
        for (int d = tid; d < D; d += NT)
            out[(size_t)b * D + d] = fmaf(s_c0[d], w0, s_c1[d] * w1);
    }
}

extern "C" void kernel_launch(void* const* d_in, const int* in_sizes, int n_in,
                              void* d_out, int out_size)
{
    const float* text        = (const float*)d_in[0];
    const float* img         = (const float*)d_in[1];
    const float* comment     = (const float*)d_in[2];
    const int*   comment_num = (const int*)d_in[3];
    const float* cow         = (const float*)d_in[4];
    const float* W_ca        = (const float*)d_in[5];
    // d_in[6] = b_ca: cancels in softmax
    const float* W_co        = (const float*)d_in[7];
    // d_in[8] = b_co: cancels in softmax
    float* out = (float*)d_out;

    dim3 g1(D / 64, (2 * B) / 64);
    gemm_cw_kernel<<<g1, 256>>>(text, img, cow);
    fuse_kernel<<<B, NT>>>(text, img, comment, comment_num, W_ca, W_co, out);
}

// round 5
// speedup vs baseline: 1.0811x; 1.0811x over previous
#include <cuda_runtime.h>
#include <math.h>

#define B 2048
#define N 128
#define D 512
#define BD (B * D)
#define NW 10            // warps per CTA in fuse kernel
#define NT (NW * 32)     // 320 threads

// 8 MB scratch for cw = content @ cow, rows interleaved: row 2b = text[b]@cow, 2b+1 = img[b]@cow
__device__ float g_cw[2 * B * D];

__device__ __forceinline__ float tanha(float x) {
    float y;
    asm("tanh.approx.f32 %0, %1;" : "=f"(y) : "f"(x));
    return y;
}
__device__ __forceinline__ float ex2(float x) {
    float y;
    asm("ex2.approx.f32 %0, %1;" : "=f"(y) : "f"(x));
    return y;
}

// Dynamic SMEM layout (floats)
#define OFF_CW0  0
#define OFF_CW1  (OFF_CW0 + D)
#define OFF_C0   (OFF_CW1 + D)
#define OFF_C1   (OFF_C0 + D)
#define OFF_BUFC (OFF_C1 + D)              // NW*D : per-warp aC
#define OFF_BA0  (OFF_BUFC + NW * D)       // NW*D : per-warp aA0
#define OFF_BA1  (OFF_BA0 + NW * D)        // NW*D : per-warp aA1
#define OFF_SS   (OFF_BA1 + NW * D)        // NW
#define OFF_R0   (OFF_SS + NW)             // NW
#define OFF_R1   (OFF_R0 + NW)             // NW
#define SMEM_FLOATS (OFF_R1 + NW)
#define SMEM_BYTES  (SMEM_FLOATS * 4)

// ---------------------------------------------------------------------------
// Kernel 1: cw[4096, 512] = A[4096, 512] @ cow[512, 512]  (fp32, near FFMA floor)
// ---------------------------------------------------------------------------
__global__ __launch_bounds__(256) void gemm_cw_kernel(
    const float* __restrict__ text,
    const float* __restrict__ img,
    const float* __restrict__ cow)
{
    __shared__ float As[16][64];
    __shared__ float Bs[16][64];

    const int tx = threadIdx.x;
    const int block_row = blockIdx.y * 64;
    const int block_col = blockIdx.x * 64;
    const int tr = (tx / 16) * 4;
    const int tc = (tx % 16) * 4;

    float acc[4][4];
#pragma unroll
    for (int i = 0; i < 4; i++)
#pragma unroll
        for (int j = 0; j < 4; j++) acc[i][j] = 0.f;

    for (int k0 = 0; k0 < D; k0 += 16) {
        {
            int m = tx >> 2;
            int kk = (tx & 3) * 4;
            int r = block_row + m;
            const float* Ap = ((r & 1) ? img : text) + (size_t)(r >> 1) * D + k0 + kk;
            float4 v = *reinterpret_cast<const float4*>(Ap);
            As[kk + 0][m] = v.x;
            As[kk + 1][m] = v.y;
            As[kk + 2][m] = v.z;
            As[kk + 3][m] = v.w;
        }
        {
            int kk = tx >> 4;
            int c = (tx & 15) * 4;
            float4 v = *reinterpret_cast<const float4*>(cow + (size_t)(k0 + kk) * D + block_col + c);
            *reinterpret_cast<float4*>(&Bs[kk][c]) = v;
        }
        __syncthreads();
#pragma unroll
        for (int k = 0; k < 16; k++) {
            float4 a4 = *reinterpret_cast<const float4*>(&As[k][tr]);
            float4 b4 = *reinterpret_cast<const float4*>(&Bs[k][tc]);
            float a[4] = {a4.x, a4.y, a4.z, a4.w};
            float b[4] = {b4.x, b4.y, b4.z, b4.w};
#pragma unroll
            for (int i = 0; i < 4; i++)
#pragma unroll
                for (int j = 0; j < 4; j++) acc[i][j] = fmaf(a[i], b[j], acc[i][j]);
        }
        __syncthreads();
    }

#pragma unroll
    for (int i = 0; i < 4; i++) {
        float4 v = make_float4(acc[i][0], acc[i][1], acc[i][2], acc[i][3]);
        *reinterpret_cast<float4*>(&g_cw[(size_t)(block_row + tr + i) * D + block_col + tc]) = v;
    }
}

// ---------------------------------------------------------------------------
// Kernel 2: one CTA (10 warps) per sample. Warp w owns row pairs
// (n, n+NW) for n = w, w+2NW, ... Pair-interleaved compute: 4 independent
// shfl-reduction chains amortize shuffle latency; cw LDS shared by the pair.
// NO shared-memory atomics: per-warp accumulators tree-reduced in epilogue.
// Branchless unshifted softmax (|logit| <= ||W_co||_1 ~ 18 fits fp32 exp).
// ---------------------------------------------------------------------------
__global__ __launch_bounds__(NT, 1) void fuse_kernel(
    const float* __restrict__ text,
    const float* __restrict__ img,
    const float* __restrict__ comment,
    const int*   __restrict__ comment_num,
    const float* __restrict__ W_ca,
    const float* __restrict__ W_co,
    float* __restrict__ out)
{
    extern __shared__ float sm[];
    const int b = blockIdx.x;
    const int tid = threadIdx.x;
    const int w = tid >> 5;
    const int lane = tid & 31;

    for (int d = tid; d < D; d += NT) {
        sm[OFF_CW0 + d] = g_cw[(size_t)(2 * b) * D + d];
        sm[OFF_CW1 + d] = g_cw[(size_t)(2 * b + 1) * D + d];
        sm[OFF_C0 + d]  = text[(size_t)b * D + d];
        sm[OFF_C1 + d]  = img[(size_t)b * D + d];
    }
    __syncthreads();

    // Hoist loop-invariant per-thread slices into registers.
    const float LOG2E = 1.4426950408889634f;
    float4 c0r[4], c1r[4], wr[4];
#pragma unroll
    for (int j = 0; j < 4; j++) {
        int q = lane + 32 * j;
        c0r[j] = reinterpret_cast<const float4*>(sm + OFF_C0)[q];
        c1r[j] = reinterpret_cast<const float4*>(sm + OFF_C1)[q];
        float4 wv = __ldg(&reinterpret_cast<const float4*>(W_co)[q]);
        wr[j] = make_float4(wv.x * LOG2E, wv.y * LOG2E, wv.z * LOG2E, wv.w * LOG2E);
    }

    const int num = comment_num[b];
    const float4* zbase = reinterpret_cast<const float4*>(comment + (size_t)b * N * D);

    float4 aA0[4], aA1[4], aC[4];
#pragma unroll
    for (int j = 0; j < 4; j++) {
        aA0[j] = make_float4(0.f, 0.f, 0.f, 0.f);
        aA1[j] = make_float4(0.f, 0.f, 0.f, 0.f);
        aC[j]  = make_float4(0.f, 0.f, 0.f, 0.f);
    }
    float ssum = 0.f;

    // Prefetch buffers for the pair (rows n, n+NW). Zero-init so an invalid
    // B-row never injects NaN into accumulators.
    float4 zA[4], zB[4];
#pragma unroll
    for (int j = 0; j < 4; j++) {
        zA[j] = make_float4(0.f, 0.f, 0.f, 0.f);
        zB[j] = make_float4(0.f, 0.f, 0.f, 0.f);
    }
    if (w < num) {
        const float4* zr = zbase + (size_t)w * (D / 4);
#pragma unroll
        for (int j = 0; j < 4; j++) zA[j] = __ldg(&zr[lane + 32 * j]);
    }
    if (w + NW < num) {
        const float4* zr = zbase + (size_t)(w + NW) * (D / 4);
#pragma unroll
        for (int j = 0; j < 4; j++) zB[j] = __ldg(&zr[lane + 32 * j]);
    }

    for (int n = w; n < num; n += 2 * NW) {
        const bool hasB = (n + NW) < num;

        // working copies; then prefetch next pair into zA/zB
        float4 zcA[4], zcB[4];
#pragma unroll
        for (int j = 0; j < 4; j++) { zcA[j] = zA[j]; zcB[j] = zB[j]; }
        if (n + 2 * NW < num) {
            const float4* zr = zbase + (size_t)(n + 2 * NW) * (D / 4);
#pragma unroll
            for (int j = 0; j < 4; j++) zA[j] = __ldg(&zr[lane + 32 * j]);
        }
        if (n + 3 * NW < num) {
            const float4* zr = zbase + (size_t)(n + 3 * NW) * (D / 4);
#pragma unroll
            for (int j = 0; j < 4; j++) zB[j] = __ldg(&zr[lane + 32 * j]);
        }

        // ---- dots with cw0/cw1 for BOTH rows (shared LDS) ----
        float dA0 = 0.f, dA1 = 0.f, dB0 = 0.f, dB1 = 0.f;
#pragma unroll
        for (int j = 0; j < 4; j++) {
            int q = lane + 32 * j;
            float4 a = reinterpret_cast<const float4*>(sm + OFF_CW0)[q];
            float4 c = reinterpret_cast<const float4*>(sm + OFF_CW1)[q];
            dA0 = fmaf(zcA[j].x, a.x, fmaf(zcA[j].y, a.y, fmaf(zcA[j].z, a.z, fmaf(zcA[j].w, a.w, dA0))));
            dA1 = fmaf(zcA[j].x, c.x, fmaf(zcA[j].y, c.y, fmaf(zcA[j].z, c.z, fmaf(zcA[j].w, c.w, dA1))));
            dB0 = fmaf(zcB[j].x, a.x, fmaf(zcB[j].y, a.y, fmaf(zcB[j].z, a.z, fmaf(zcB[j].w, a.w, dB0))));
            dB1 = fmaf(zcB[j].x, c.x, fmaf(zcB[j].y, c.y, fmaf(zcB[j].z, c.z, fmaf(zcB[j].w, c.w, dB1))));
        }
        // 4 interleaved shfl reduction chains
#pragma unroll
        for (int off = 16; off; off >>= 1) {
            dA0 += __shfl_xor_sync(0xffffffffu, dA0, off);
            dA1 += __shfl_xor_sync(0xffffffffu, dA1, off);
            dB0 += __shfl_xor_sync(0xffffffffu, dB0, off);
            dB1 += __shfl_xor_sync(0xffffffffu, dB1, off);
        }
        float t0A = tanha(dA0), t1A = tanha(dA1);
        float t0B = tanha(dB0), t1B = tanha(dB1);
        if (!hasB) { t0B = 0.f; t1B = 0.f; }

        // ---- logits + accA for both rows ----
        float lpA = 0.f, lpB = 0.f;
#pragma unroll
        for (int j = 0; j < 4; j++) {
            float zt;
            zt = tanha(fmaf(t0A, c0r[j].x, fmaf(t1A, c1r[j].x, zcA[j].x))); lpA = fmaf(zt, wr[j].x, lpA);
            zt = tanha(fmaf(t0B, c0r[j].x, fmaf(t1B, c1r[j].x, zcB[j].x))); lpB = fmaf(zt, wr[j].x, lpB);
            zt = tanha(fmaf(t0A, c0r[j].y, fmaf(t1A, c1r[j].y, zcA[j].y))); lpA = fmaf(zt, wr[j].y, lpA);
            zt = tanha(fmaf(t0B, c0r[j].y, fmaf(t1B, c1r[j].y, zcB[j].y))); lpB = fmaf(zt, wr[j].y, lpB);
            zt = tanha(fmaf(t0A, c0r[j].z, fmaf(t1A, c1r[j].z, zcA[j].z))); lpA = fmaf(zt, wr[j].z, lpA);
            zt = tanha(fmaf(t0B, c0r[j].z, fmaf(t1B, c1r[j].z, zcB[j].z))); lpB = fmaf(zt, wr[j].z, lpB);
            zt = tanha(fmaf(t0A, c0r[j].w, fmaf(t1A, c1r[j].w, zcA[j].w))); lpA = fmaf(zt, wr[j].w, lpA);
            zt = tanha(fmaf(t0B, c0r[j].w, fmaf(t1B, c1r[j].w, zcB[j].w))); lpB = fmaf(zt, wr[j].w, lpB);

            aA0[j].x = fmaf(t0A, zcA[j].x, fmaf(t0B, zcB[j].x, aA0[j].x));
            aA0[j].y = fmaf(t0A, zcA[j].y, fmaf(t0B, zcB[j].y, aA0[j].y));
            aA0[j].z = fmaf(t0A, zcA[j].z, fmaf(t0B, zcB[j].z, aA0[j].z));
            aA0[j].w = fmaf(t0A, zcA[j].w, fmaf(t0B, zcB[j].w, aA0[j].w));
            aA1[j].x = fmaf(t1A, zcA[j].x, fmaf(t1B, zcB[j].x, aA1[j].x));
            aA1[j].y = fmaf(t1A, zcA[j].y, fmaf(t1B, zcB[j].y, aA1[j].y));
            aA1[j].z = fmaf(t1A, zcA[j].z, fmaf(t1B, zcB[j].z, aA1[j].z));
            aA1[j].w = fmaf(t1A, zcA[j].w, fmaf(t1B, zcB[j].w, aA1[j].w));
        }
#pragma unroll
        for (int off = 16; off; off >>= 1) {
            lpA += __shfl_xor_sync(0xffffffffu, lpA, off);
            lpB += __shfl_xor_sync(0xffffffffu, lpB, off);
        }
        float eA = ex2(lpA);
        float eB = hasB ? ex2(lpB) : 0.f;
        ssum += eA + eB;
#pragma unroll
        for (int j = 0; j < 4; j++) {
            aC[j].x = fmaf(eA, zcA[j].x, fmaf(eB, zcB[j].x, aC[j].x));
            aC[j].y = fmaf(eA, zcA[j].y, fmaf(eB, zcB[j].y, aC[j].y));
            aC[j].z = fmaf(eA, zcA[j].z, fmaf(eB, zcB[j].z, aC[j].z));
            aC[j].w = fmaf(eA, zcA[j].w, fmaf(eB, zcB[j].w, aC[j].w));
        }
    }

    // ---- stash per-warp state (vector STS, no atomics) ----
    if (lane == 0) sm[OFF_SS + w] = ssum;
#pragma unroll
    for (int j = 0; j < 4; j++) {
        int q = lane + 32 * j;
        reinterpret_cast<float4*>(sm + OFF_BUFC + w * D)[q] = aC[j];
        reinterpret_cast<float4*>(sm + OFF_BA0 + w * D)[q]  = aA0[j];
        reinterpret_cast<float4*>(sm + OFF_BA1 + w * D)[q]  = aA1[j];
    }
    __syncthreads();

    // ---- epilogue: tree-reduce across warps, content logits, outputs ----
    float S = 0.f;
#pragma unroll
    for (int i = 0; i < NW; i++) S += sm[OFF_SS + i];
    float invS = __frcp_rn(S);

    float p0 = 0.f, p1 = 0.f;
    for (int d = tid; d < D; d += NT) {
        float rc = 0.f, a0 = 0.f, a1 = 0.f;
#pragma unroll
        for (int i = 0; i < NW; i++) {
            rc += sm[OFF_BUFC + i * D + d];
            a0 += sm[OFF_BA0 + i * D + d];
            a1 += sm[OFF_BA1 + i * D + d];
        }
        out[BD + (size_t)b * D + d] = rc * invS;
        float wca = __ldg(&W_ca[d]);
        p0 = fmaf(tanha(sm[OFF_C0 + d] + a0), wca, p0);
        p1 = fmaf(tanha(sm[OFF_C1 + d] + a1), wca, p1);
    }
#pragma unroll
    for (int off = 16; off; off >>= 1) {
        p0 += __shfl_xor_sync(0xffffffffu, p0, off);
        p1 += __shfl_xor_sync(0xffffffffu, p1, off);
    }
    if (lane == 0) { sm[OFF_R0 + w] = p0; sm[OFF_R1 + w] = p1; }
    __syncthreads();

    float L0 = 0.f, L1 = 0.f;
#pragma unroll
    for (int i = 0; i < NW; i++) { L0 += sm[OFF_R0 + i]; L1 += sm[OFF_R1 + i]; }
    float mm = fmaxf(L0, L1);
    float e0 = __expf(L0 - mm), e1 = __expf(L1 - mm);
    float inv2 = __frcp_rn(e0 + e1);
    float w0 = e0 * inv2, w1 = e1 * inv2;
    if (tid == 0) {
        out[2 * BD + 2 * b + 0] = w0;
        out[2 * BD + 2 * b + 1] = w1;
    }
    for (int d = tid; d < D; d += NT)
        out[(size_t)b * D + d] = fmaf(sm[OFF_C0 + d], w0, sm[OFF_C1 + d] * w1);
}

extern "C" void kernel_launch(void* const* d_in, const int* in_sizes, int n_in,
                              void* d_out, int out_size)
{
    const float* text        = (const float*)d_in[0];
    const float* img         = (const float*)d_in[1];
    const float* comment     = (const float*)d_in[2];
    const int*   comment_num = (const int*)d_in[3];
    const float* cow         = (const float*)d_in[4];
    const float* W_ca        = (const float*)d_in[5];
    // d_in[6] = b_ca: cancels in softmax
    const float* W_co        = (const float*)d_in[7];
    // d_in[8] = b_co: cancels in softmax
    float* out = (float*)d_out;

    cudaFuncSetAttribute(fuse_kernel, cudaFuncAttributeMaxDynamicSharedMemorySize, SMEM_BYTES);

    dim3 g1(D / 64, (2 * B) / 64);
    gemm_cw_kernel<<<g1, 256>>>(text, img, cow);
    fuse_kernel<<<B, NT, SMEM_BYTES>>>(text, img, comment, comment_num, W_ca, W_co, out);
}

// round 6
// speedup vs baseline: 1.3131x; 1.2146x over previous
#include <cuda_runtime.h>
#include <math.h>

#define B 2048
#define N 128
#define D 512
#define BD (B * D)
#define NW 16            // warps per CTA in fuse kernel
#define NT (NW * 32)     // 512 threads

// 8 MB scratch for cw = content @ cow, rows interleaved: row 2b = text[b]@cow, 2b+1 = img[b]@cow
__device__ float g_cw[2 * B * D];

__device__ __forceinline__ float tanha(float x) {
    float y;
    asm("tanh.approx.f32 %0, %1;" : "=f"(y) : "f"(x));
    return y;
}
__device__ __forceinline__ float ex2(float x) {
    float y;
    asm("ex2.approx.f32 %0, %1;" : "=f"(y) : "f"(x));
    return y;
}

// Dynamic SMEM layout (floats)
#define OFF_CW0  0
#define OFF_CW1  (OFF_CW0 + D)
#define OFF_C0   (OFF_CW1 + D)
#define OFF_C1   (OFF_C0 + D)
#define OFF_BUFC (OFF_C1 + D)              // NW*D : per-warp aC
#define OFF_BA0  (OFF_BUFC + NW * D)       // NW*D : per-warp aA0
#define OFF_BA1  (OFF_BA0 + NW * D)        // NW*D : per-warp aA1
#define OFF_SS   (OFF_BA1 + NW * D)        // NW
#define OFF_R0   (OFF_SS + NW)             // NW
#define OFF_R1   (OFF_R0 + NW)             // NW
#define SMEM_FLOATS (OFF_R1 + NW)
#define SMEM_BYTES  (SMEM_FLOATS * 4)

// ---------------------------------------------------------------------------
// Kernel 1: cw[4096, 512] = A[4096, 512] @ cow[512, 512]  (fp32)
// ---------------------------------------------------------------------------
__global__ __launch_bounds__(256) void gemm_cw_kernel(
    const float* __restrict__ text,
    const float* __restrict__ img,
    const float* __restrict__ cow)
{
    __shared__ float As[16][64];
    __shared__ float Bs[16][64];

    const int tx = threadIdx.x;
    const int block_row = blockIdx.y * 64;
    const int block_col = blockIdx.x * 64;
    const int tr = (tx / 16) * 4;
    const int tc = (tx % 16) * 4;

    float acc[4][4];
#pragma unroll
    for (int i = 0; i < 4; i++)
#pragma unroll
        for (int j = 0; j < 4; j++) acc[i][j] = 0.f;

    for (int k0 = 0; k0 < D; k0 += 16) {
        {
            int m = tx >> 2;
            int kk = (tx & 3) * 4;
            int r = block_row + m;
            const float* Ap = ((r & 1) ? img : text) + (size_t)(r >> 1) * D + k0 + kk;
            float4 v = *reinterpret_cast<const float4*>(Ap);
            As[kk + 0][m] = v.x;
            As[kk + 1][m] = v.y;
            As[kk + 2][m] = v.z;
            As[kk + 3][m] = v.w;
        }
        {
            int kk = tx >> 4;
            int c = (tx & 15) * 4;
            float4 v = *reinterpret_cast<const float4*>(cow + (size_t)(k0 + kk) * D + block_col + c);
            *reinterpret_cast<float4*>(&Bs[kk][c]) = v;
        }
        __syncthreads();
#pragma unroll
        for (int k = 0; k < 16; k++) {
            float4 a4 = *reinterpret_cast<const float4*>(&As[k][tr]);
            float4 b4 = *reinterpret_cast<const float4*>(&Bs[k][tc]);
            float a[4] = {a4.x, a4.y, a4.z, a4.w};
            float b[4] = {b4.x, b4.y, b4.z, b4.w};
#pragma unroll
            for (int i = 0; i < 4; i++)
#pragma unroll
                for (int j = 0; j < 4; j++) acc[i][j] = fmaf(a[i], b[j], acc[i][j]);
        }
        __syncthreads();
    }

#pragma unroll
    for (int i = 0; i < 4; i++) {
        float4 v = make_float4(acc[i][0], acc[i][1], acc[i][2], acc[i][3]);
        *reinterpret_cast<float4*>(&g_cw[(size_t)(block_row + tr + i) * D + block_col + tc]) = v;
    }
}

// ---------------------------------------------------------------------------
// Kernel 2: one CTA (16 warps, 512 thr, <=128 regs) per sample.
// Warp w owns rows n = w, w+NW, ... Single-row loop; c0/c1 read from SMEM
// (register budget spent on warps, not hoisting); W_co*log2e in registers.
// No atomics: per-warp accumulators tree-reduced in epilogue.
// Branchless unshifted softmax (|logit| <= ||W_co||_1 ~ 18 fits fp32 exp).
// ---------------------------------------------------------------------------
__global__ __launch_bounds__(NT, 1) void fuse_kernel(
    const float* __restrict__ text,
    const float* __restrict__ img,
    const float* __restrict__ comment,
    const int*   __restrict__ comment_num,
    const float* __restrict__ W_ca,
    const float* __restrict__ W_co,
    float* __restrict__ out)
{
    extern __shared__ float sm[];
    const int b = blockIdx.x;
    const int tid = threadIdx.x;
    const int w = tid >> 5;
    const int lane = tid & 31;

    for (int d = tid; d < D; d += NT) {
        sm[OFF_CW0 + d] = g_cw[(size_t)(2 * b) * D + d];
        sm[OFF_CW1 + d] = g_cw[(size_t)(2 * b + 1) * D + d];
        sm[OFF_C0 + d]  = text[(size_t)b * D + d];
        sm[OFF_C1 + d]  = img[(size_t)b * D + d];
    }
    __syncthreads();

    const float LOG2E = 1.4426950408889634f;
    float4 wr[4];
#pragma unroll
    for (int j = 0; j < 4; j++) {
        float4 wv = __ldg(&reinterpret_cast<const float4*>(W_co)[lane + 32 * j]);
        wr[j] = make_float4(wv.x * LOG2E, wv.y * LOG2E, wv.z * LOG2E, wv.w * LOG2E);
    }

    const int num = comment_num[b];
    const float4* zbase = reinterpret_cast<const float4*>(comment + (size_t)b * N * D);

    float4 aA0[4], aA1[4], aC[4];
#pragma unroll
    for (int j = 0; j < 4; j++) {
        aA0[j] = make_float4(0.f, 0.f, 0.f, 0.f);
        aA1[j] = make_float4(0.f, 0.f, 0.f, 0.f);
        aC[j]  = make_float4(0.f, 0.f, 0.f, 0.f);
    }
    float ssum = 0.f;

    // prefetch first row for this warp
    float4 zb[4];
    if (w < num) {
        const float4* zr = zbase + (size_t)w * (D / 4);
#pragma unroll
        for (int j = 0; j < 4; j++) zb[j] = __ldg(&zr[lane + 32 * j]);
    }

    for (int n = w; n < num; n += NW) {
        float4 zc[4];
#pragma unroll
        for (int j = 0; j < 4; j++) zc[j] = zb[j];

        int nn = n + NW;
        if (nn < num) {
            const float4* zr = zbase + (size_t)nn * (D / 4);
#pragma unroll
            for (int j = 0; j < 4; j++) zb[j] = __ldg(&zr[lane + 32 * j]);
        }

        // dots with cw0, cw1 (SMEM), two partial chains each
        float d0a = 0.f, d0b = 0.f, d1a = 0.f, d1b = 0.f;
#pragma unroll
        for (int j = 0; j < 2; j++) {
            int q0 = lane + 32 * j;
            int q1 = lane + 32 * (j + 2);
            float4 a0 = reinterpret_cast<const float4*>(sm + OFF_CW0)[q0];
            float4 a1 = reinterpret_cast<const float4*>(sm + OFF_CW0)[q1];
            float4 c0 = reinterpret_cast<const float4*>(sm + OFF_CW1)[q0];
            float4 c1 = reinterpret_cast<const float4*>(sm + OFF_CW1)[q1];
            d0a = fmaf(zc[j].x, a0.x, fmaf(zc[j].y, a0.y, fmaf(zc[j].z, a0.z, fmaf(zc[j].w, a0.w, d0a))));
            d0b = fmaf(zc[j+2].x, a1.x, fmaf(zc[j+2].y, a1.y, fmaf(zc[j+2].z, a1.z, fmaf(zc[j+2].w, a1.w, d0b))));
            d1a = fmaf(zc[j].x, c0.x, fmaf(zc[j].y, c0.y, fmaf(zc[j].z, c0.z, fmaf(zc[j].w, c0.w, d1a))));
            d1b = fmaf(zc[j+2].x, c1.x, fmaf(zc[j+2].y, c1.y, fmaf(zc[j+2].z, c1.z, fmaf(zc[j+2].w, c1.w, d1b))));
        }
        float d0 = d0a + d0b, d1 = d1a + d1b;
#pragma unroll
        for (int off = 16; off; off >>= 1) {
            d0 += __shfl_xor_sync(0xffffffffu, d0, off);
            d1 += __shfl_xor_sync(0xffffffffu, d1, off);
        }
        float t0 = tanha(d0);
        float t1 = tanha(d1);

        // logit + accA (c0/c1 from SMEM)
        float lpa = 0.f, lpb = 0.f;
#pragma unroll
        for (int j = 0; j < 4; j++) {
            int q = lane + 32 * j;
            float4 c0 = reinterpret_cast<const float4*>(sm + OFF_C0)[q];
            float4 c1 = reinterpret_cast<const float4*>(sm + OFF_C1)[q];
            float zt;
            zt = tanha(fmaf(t0, c0.x, fmaf(t1, c1.x, zc[j].x))); lpa = fmaf(zt, wr[j].x, lpa);
            zt = tanha(fmaf(t0, c0.y, fmaf(t1, c1.y, zc[j].y))); lpb = fmaf(zt, wr[j].y, lpb);
            zt = tanha(fmaf(t0, c0.z, fmaf(t1, c1.z, zc[j].z))); lpa = fmaf(zt, wr[j].z, lpa);
            zt = tanha(fmaf(t0, c0.w, fmaf(t1, c1.w, zc[j].w))); lpb = fmaf(zt, wr[j].w, lpb);
            aA0[j].x = fmaf(t0, zc[j].x, aA0[j].x);
            aA0[j].y = fmaf(t0, zc[j].y, aA0[j].y);
            aA0[j].z = fmaf(t0, zc[j].z, aA0[j].z);
            aA0[j].w = fmaf(t0, zc[j].w, aA0[j].w);
            aA1[j].x = fmaf(t1, zc[j].x, aA1[j].x);
            aA1[j].y = fmaf(t1, zc[j].y, aA1[j].y);
            aA1[j].z = fmaf(t1, zc[j].z, aA1[j].z);
            aA1[j].w = fmaf(t1, zc[j].w, aA1[j].w);
        }
        float lp = lpa + lpb;
#pragma unroll
        for (int off = 16; off; off >>= 1)
            lp += __shfl_xor_sync(0xffffffffu, lp, off);
        float e = ex2(lp);
        ssum += e;
#pragma unroll
        for (int j = 0; j < 4; j++) {
            aC[j].x = fmaf(e, zc[j].x, aC[j].x);
            aC[j].y = fmaf(e, zc[j].y, aC[j].y);
            aC[j].z = fmaf(e, zc[j].z, aC[j].z);
            aC[j].w = fmaf(e, zc[j].w, aC[j].w);
        }
    }

    // ---- stash per-warp state (vector STS, no atomics) ----
    if (lane == 0) sm[OFF_SS + w] = ssum;
#pragma unroll
    for (int j = 0; j < 4; j++) {
        int q = lane + 32 * j;
        reinterpret_cast<float4*>(sm + OFF_BUFC + w * D)[q] = aC[j];
        reinterpret_cast<float4*>(sm + OFF_BA0 + w * D)[q]  = aA0[j];
        reinterpret_cast<float4*>(sm + OFF_BA1 + w * D)[q]  = aA1[j];
    }
    __syncthreads();

    // ---- epilogue: tree-reduce across warps, content logits, outputs ----
    float S = 0.f;
#pragma unroll
    for (int i = 0; i < NW; i++) S += sm[OFF_SS + i];
    float invS = __frcp_rn(S);

    // each thread owns exactly one d (NT == D)
    const int d = tid;
    float rc = 0.f, a0 = 0.f, a1 = 0.f;
#pragma unroll
    for (int i = 0; i < NW; i++) {
        rc += sm[OFF_BUFC + i * D + d];
        a0 += sm[OFF_BA0 + i * D + d];
        a1 += sm[OFF_BA1 + i * D + d];
    }
    out[BD + (size_t)b * D + d] = rc * invS;
    float wca = __ldg(&W_ca[d]);
    float p0 = tanha(sm[OFF_C0 + d] + a0) * wca;
    float p1 = tanha(sm[OFF_C1 + d] + a1) * wca;
#pragma unroll
    for (int off = 16; off; off >>= 1) {
        p0 += __shfl_xor_sync(0xffffffffu, p0, off);
        p1 += __shfl_xor_sync(0xffffffffu, p1, off);
    }
    if (lane == 0) { sm[OFF_R0 + w] = p0; sm[OFF_R1 + w] = p1; }
    __syncthreads();

    float L0 = 0.f, L1 = 0.f;
#pragma unroll
    for (int i = 0; i < NW; i++) { L0 += sm[OFF_R0 + i]; L1 += sm[OFF_R1 + i]; }
    float mm = fmaxf(L0, L1);
    float e0 = __expf(L0 - mm), e1 = __expf(L1 - mm);
    float inv2 = __frcp_rn(e0 + e1);
    float w0 = e0 * inv2, w1 = e1 * inv2;
    if (tid == 0) {
        out[2 * BD + 2 * b + 0] = w0;
        out[2 * BD + 2 * b + 1] = w1;
    }
    out[(size_t)b * D + d] = fmaf(sm[OFF_C0 + d], w0, sm[OFF_C1 + d] * w1);
}

extern "C" void kernel_launch(void* const* d_in, const int* in_sizes, int n_in,
                              void* d_out, int out_size)
{
    const float* text        = (const float*)d_in[0];
    const float* img         = (const float*)d_in[1];
    const float* comment     = (const float*)d_in[2];
    const int*   comment_num = (const int*)d_in[3];
    const float* cow         = (const float*)d_in[4];
    const float* W_ca        = (const float*)d_in[5];
    // d_in[6] = b_ca: cancels in softmax
    const float* W_co        = (const float*)d_in[7];
    // d_in[8] = b_co: cancels in softmax
    float* out = (float*)d_out;

    cudaFuncSetAttribute(fuse_kernel, cudaFuncAttributeMaxDynamicSharedMemorySize, SMEM_BYTES);

    dim3 g1(D / 64, (2 * B) / 64);
    gemm_cw_kernel<<<g1, 256>>>(text, img, cow);
    fuse_kernel<<<B, NT, SMEM_BYTES>>>(text, img, comment, comment_num, W_ca, W_co, out);
}

// round 7
// speedup vs baseline: 1.6094x; 1.2256x over previous
#include <cuda_runtime.h>
#include <math.h>
#include <stdint.h>

#define B 2048
#define N 128
#define D 512
#define BD (B * D)
#define NW 8             // warps per CTA in fuse kernel
#define NT (NW * 32)     // 256 threads

// 8 MB scratch for cw = content @ cow, rows interleaved: row 2b = text[b]@cow, 2b+1 = img[b]@cow
__device__ float g_cw[2 * B * D];

__device__ __forceinline__ float tanha(float x) {
    float y;
    asm("tanh.approx.f32 %0, %1;" : "=f"(y) : "f"(x));
    return y;
}
__device__ __forceinline__ float ex2(float x) {
    float y;
    asm("ex2.approx.f32 %0, %1;" : "=f"(y) : "f"(x));
    return y;
}
__device__ __forceinline__ uint32_t f2tf32(float x) {
    uint32_t r;
    asm("cvt.rna.tf32.f32 %0, %1;" : "=r"(r) : "f"(x));
    return r;
}
__device__ __forceinline__ void mma_tf32(float c[4], const uint32_t a[4], const uint32_t b[2]) {
    asm volatile(
        "mma.sync.aligned.m16n8k8.row.col.f32.tf32.tf32.f32 "
        "{%0,%1,%2,%3}, {%4,%5,%6,%7}, {%8,%9}, {%0,%1,%2,%3};"
        : "+f"(c[0]), "+f"(c[1]), "+f"(c[2]), "+f"(c[3])
        : "r"(a[0]), "r"(a[1]), "r"(a[2]), "r"(a[3]), "r"(b[0]), "r"(b[1]));
}

// Dynamic SMEM layout for fuse kernel (floats)
#define OFF_CW0  0
#define OFF_CW1  (OFF_CW0 + D)
#define OFF_C0   (OFF_CW1 + D)
#define OFF_C1   (OFF_C0 + D)
#define OFF_BUFC (OFF_C1 + D)              // NW*D : per-warp aC
#define OFF_BA0  (OFF_BUFC + NW * D)       // NW*D : per-warp aA0
#define OFF_BA1  (OFF_BA0 + NW * D)        // NW*D : per-warp aA1
#define OFF_SS   (OFF_BA1 + NW * D)        // NW
#define OFF_R0   (OFF_SS + NW)             // NW
#define OFF_R1   (OFF_R0 + NW)             // NW
#define SMEM_FLOATS (OFF_R1 + NW)
#define SMEM_BYTES  (SMEM_FLOATS * 4)

// ---------------------------------------------------------------------------
// Kernel 1: cw[4096,512] = A[4096,512] @ cow[512,512] via tf32x3 mma.sync.
// CTA: 256 thr (8 warps), tile M=128 N=128 K=32. Warp grid 4(m)x2(n):
// each warp computes 32x64 = 2 m16-frags x 8 n8-frags.
// tf32x3: x = hi + lo; D += Alo*Bhi + Ahi*Blo + Ahi*Bhi  (error ~2^-21).
// ---------------------------------------------------------------------------
#define GM_KT 32
#define GM_LD 132   // padded row stride

__global__ __launch_bounds__(256) void gemm_cw_tf32(
    const float* __restrict__ text,
    const float* __restrict__ img,
    const float* __restrict__ cow)
{
    __shared__ float As[GM_KT][GM_LD];  // [k][m]
    __shared__ float Ws[GM_KT][GM_LD];  // [k][n]

    const int t = threadIdx.x;
    const int wid = t >> 5;
    const int lane = t & 31;
    const int warp_m = (wid & 3) * 32;
    const int warp_n = (wid >> 2) * 64;
    const int brow = blockIdx.y * 128;
    const int bcol = blockIdx.x * 128;
    const int g  = lane >> 2;   // 0..7
    const int tg = lane & 3;    // 0..3

    float c[2][8][4];
#pragma unroll
    for (int mi = 0; mi < 2; mi++)
#pragma unroll
        for (int ni = 0; ni < 8; ni++)
#pragma unroll
            for (int j = 0; j < 4; j++) c[mi][ni][j] = 0.f;

    for (int k0 = 0; k0 < D; k0 += GM_KT) {
        // Load A tile (128 rows x 32 k), k-major in SMEM
#pragma unroll
        for (int s = 0; s < 4; s++) {
            int f = t + 256 * s;
            int r = f >> 3;
            int kk = (f & 7) * 4;
            int gr = brow + r;
            const float* Ap = ((gr & 1) ? img : text) + (size_t)(gr >> 1) * D + k0 + kk;
            float4 v = *reinterpret_cast<const float4*>(Ap);
            As[kk + 0][r] = v.x;
            As[kk + 1][r] = v.y;
            As[kk + 2][r] = v.z;
            As[kk + 3][r] = v.w;
        }
        // Load W tile (32 k x 128 n)
#pragma unroll
        for (int s = 0; s < 4; s++) {
            int f = t + 256 * s;
            int kk = f >> 5;
            int n = (f & 31) * 4;
            float4 v = *reinterpret_cast<const float4*>(cow + (size_t)(k0 + kk) * D + bcol + n);
            *reinterpret_cast<float4*>(&Ws[kk][n]) = v;
        }
        __syncthreads();

#pragma unroll
        for (int k8 = 0; k8 < GM_KT; k8 += 8) {
            // A fragments (hi/lo)
            uint32_t ahi[2][4], alo[2][4];
#pragma unroll
            for (int mi = 0; mi < 2; mi++) {
                int r0 = warp_m + mi * 16;
                float av[4];
                av[0] = As[k8 + tg    ][r0 + g];
                av[1] = As[k8 + tg    ][r0 + 8 + g];
                av[2] = As[k8 + tg + 4][r0 + g];
                av[3] = As[k8 + tg + 4][r0 + 8 + g];
#pragma unroll
                for (int j = 0; j < 4; j++) {
                    uint32_t h = f2tf32(av[j]);
                    ahi[mi][j] = h;
                    alo[mi][j] = __float_as_uint(av[j] - __uint_as_float(h));
                }
            }
            // B fragments (hi/lo)
            uint32_t bhi[8][2], blo[8][2];
#pragma unroll
            for (int ni = 0; ni < 8; ni++) {
                int n0 = warp_n + ni * 8;
                float bv[2];
                bv[0] = Ws[k8 + tg    ][n0 + g];
                bv[1] = Ws[k8 + tg + 4][n0 + g];
#pragma unroll
                for (int j = 0; j < 2; j++) {
                    uint32_t h = f2tf32(bv[j]);
                    bhi[ni][j] = h;
                    blo[ni][j] = __float_as_uint(bv[j] - __uint_as_float(h));
                }
            }
#pragma unroll
            for (int mi = 0; mi < 2; mi++)
#pragma unroll
                for (int ni = 0; ni < 8; ni++) {
                    mma_tf32(c[mi][ni], alo[mi], bhi[ni]);
                    mma_tf32(c[mi][ni], ahi[mi], blo[ni]);
                    mma_tf32(c[mi][ni], ahi[mi], bhi[ni]);
                }
        }
        __syncthreads();
    }

    // Store C: c[mi][ni] = {(row g, col 2tg), (g, 2tg+1), (g+8, 2tg), (g+8, 2tg+1)}
#pragma unroll
    for (int mi = 0; mi < 2; mi++)
#pragma unroll
        for (int ni = 0; ni < 8; ni++) {
            int row = brow + warp_m + mi * 16 + g;
            int col = bcol + warp_n + ni * 8 + 2 * tg;
            float2 v0 = make_float2(c[mi][ni][0], c[mi][ni][1]);
            float2 v1 = make_float2(c[mi][ni][2], c[mi][ni][3]);
            *reinterpret_cast<float2*>(&g_cw[(size_t)row * D + col]) = v0;
            *reinterpret_cast<float2*>(&g_cw[(size_t)(row + 8) * D + col]) = v1;
        }
}

// ---------------------------------------------------------------------------
// Kernel 2: one CTA (8 warps, 256 thr, <=128 regs, 2 CTAs/SM) per sample.
// Warp w owns rows n = w, w+NW, ... No atomics; per-warp accumulators
// tree-reduced in epilogue. Branchless unshifted softmax.
// ---------------------------------------------------------------------------
__global__ __launch_bounds__(NT, 2) void fuse_kernel(
    const float* __restrict__ text,
    const float* __restrict__ img,
    const float* __restrict__ comment,
    const int*   __restrict__ comment_num,
    const float* __restrict__ W_ca,
    const float* __restrict__ W_co,
    float* __restrict__ out)
{
    extern __shared__ float sm[];
    const int b = blockIdx.x;
    const int tid = threadIdx.x;
    const int w = tid >> 5;
    const int lane = tid & 31;

    for (int d = tid; d < D; d += NT) {
        sm[OFF_CW0 + d] = g_cw[(size_t)(2 * b) * D + d];
        sm[OFF_CW1 + d] = g_cw[(size_t)(2 * b + 1) * D + d];
        sm[OFF_C0 + d]  = text[(size_t)b * D + d];
        sm[OFF_C1 + d]  = img[(size_t)b * D + d];
    }
    __syncthreads();

    const float LOG2E = 1.4426950408889634f;
    float4 wr[4];
#pragma unroll
    for (int j = 0; j < 4; j++) {
        float4 wv = __ldg(&reinterpret_cast<const float4*>(W_co)[lane + 32 * j]);
        wr[j] = make_float4(wv.x * LOG2E, wv.y * LOG2E, wv.z * LOG2E, wv.w * LOG2E);
    }

    const int num = comment_num[b];
    const float4* zbase = reinterpret_cast<const float4*>(comment + (size_t)b * N * D);

    float4 aA0[4], aA1[4], aC[4];
#pragma unroll
    for (int j = 0; j < 4; j++) {
        aA0[j] = make_float4(0.f, 0.f, 0.f, 0.f);
        aA1[j] = make_float4(0.f, 0.f, 0.f, 0.f);
        aC[j]  = make_float4(0.f, 0.f, 0.f, 0.f);
    }
    float ssum = 0.f;

    // prefetch first row for this warp
    float4 zb[4];
    if (w < num) {
        const float4* zr = zbase + (size_t)w * (D / 4);
#pragma unroll
        for (int j = 0; j < 4; j++) zb[j] = __ldg(&zr[lane + 32 * j]);
    }

    for (int n = w; n < num; n += NW) {
        float4 zc[4];
#pragma unroll
        for (int j = 0; j < 4; j++) zc[j] = zb[j];

        int nn = n + NW;
        if (nn < num) {
            const float4* zr = zbase + (size_t)nn * (D / 4);
#pragma unroll
            for (int j = 0; j < 4; j++) zb[j] = __ldg(&zr[lane + 32 * j]);
        }

        // dots with cw0, cw1 (SMEM), two partial chains each
        float d0a = 0.f, d0b = 0.f, d1a = 0.f, d1b = 0.f;
#pragma unroll
        for (int j = 0; j < 2; j++) {
            int q0 = lane + 32 * j;
            int q1 = lane + 32 * (j + 2);
            float4 a0 = reinterpret_cast<const float4*>(sm + OFF_CW0)[q0];
            float4 a1 = reinterpret_cast<const float4*>(sm + OFF_CW0)[q1];
            float4 c0 = reinterpret_cast<const float4*>(sm + OFF_CW1)[q0];
            float4 c1 = reinterpret_cast<const float4*>(sm + OFF_CW1)[q1];
            d0a = fmaf(zc[j].x, a0.x, fmaf(zc[j].y, a0.y, fmaf(zc[j].z, a0.z, fmaf(zc[j].w, a0.w, d0a))));
            d0b = fmaf(zc[j+2].x, a1.x, fmaf(zc[j+2].y, a1.y, fmaf(zc[j+2].z, a1.z, fmaf(zc[j+2].w, a1.w, d0b))));
            d1a = fmaf(zc[j].x, c0.x, fmaf(zc[j].y, c0.y, fmaf(zc[j].z, c0.z, fmaf(zc[j].w, c0.w, d1a))));
            d1b = fmaf(zc[j+2].x, c1.x, fmaf(zc[j+2].y, c1.y, fmaf(zc[j+2].z, c1.z, fmaf(zc[j+2].w, c1.w, d1b))));
        }
        float d0 = d0a + d0b, d1 = d1a + d1b;
#pragma unroll
        for (int off = 16; off; off >>= 1) {
            d0 += __shfl_xor_sync(0xffffffffu, d0, off);
            d1 += __shfl_xor_sync(0xffffffffu, d1, off);
        }
        float t0 = tanha(d0);
        float t1 = tanha(d1);

        // logit + accA (c0/c1 from SMEM)
        float lpa = 0.f, lpb = 0.f;
#pragma unroll
        for (int j = 0; j < 4; j++) {
            int q = lane + 32 * j;
            float4 c0 = reinterpret_cast<const float4*>(sm + OFF_C0)[q];
            float4 c1 = reinterpret_cast<const float4*>(sm + OFF_C1)[q];
            float zt;
            zt = tanha(fmaf(t0, c0.x, fmaf(t1, c1.x, zc[j].x))); lpa = fmaf(zt, wr[j].x, lpa);
            zt = tanha(fmaf(t0, c0.y, fmaf(t1, c1.y, zc[j].y))); lpb = fmaf(zt, wr[j].y, lpb);
            zt = tanha(fmaf(t0, c0.z, fmaf(t1, c1.z, zc[j].z))); lpa = fmaf(zt, wr[j].z, lpa);
            zt = tanha(fmaf(t0, c0.w, fmaf(t1, c1.w, zc[j].w))); lpb = fmaf(zt, wr[j].w, lpb);
            aA0[j].x = fmaf(t0, zc[j].x, aA0[j].x);
            aA0[j].y = fmaf(t0, zc[j].y, aA0[j].y);
            aA0[j].z = fmaf(t0, zc[j].z, aA0[j].z);
            aA0[j].w = fmaf(t0, zc[j].w, aA0[j].w);
            aA1[j].x = fmaf(t1, zc[j].x, aA1[j].x);
            aA1[j].y = fmaf(t1, zc[j].y, aA1[j].y);
            aA1[j].z = fmaf(t1, zc[j].z, aA1[j].z);
            aA1[j].w = fmaf(t1, zc[j].w, aA1[j].w);
        }
        float lp = lpa + lpb;
#pragma unroll
        for (int off = 16; off; off >>= 1)
            lp += __shfl_xor_sync(0xffffffffu, lp, off);
        float e = ex2(lp);
        ssum += e;
#pragma unroll
        for (int j = 0; j < 4; j++) {
            aC[j].x = fmaf(e, zc[j].x, aC[j].x);
            aC[j].y = fmaf(e, zc[j].y, aC[j].y);
            aC[j].z = fmaf(e, zc[j].z, aC[j].z);
            aC[j].w = fmaf(e, zc[j].w, aC[j].w);
        }
    }

    // ---- stash per-warp state (vector STS, no atomics) ----
    if (lane == 0) sm[OFF_SS + w] = ssum;
#pragma unroll
    for (int j = 0; j < 4; j++) {
        int q = lane + 32 * j;
        reinterpret_cast<float4*>(sm + OFF_BUFC + w * D)[q] = aC[j];
        reinterpret_cast<float4*>(sm + OFF_BA0 + w * D)[q]  = aA0[j];
        reinterpret_cast<float4*>(sm + OFF_BA1 + w * D)[q]  = aA1[j];
    }
    __syncthreads();

    // ---- epilogue: tree-reduce across warps, content logits, outputs ----
    float S = 0.f;
#pragma unroll
    for (int i = 0; i < NW; i++) S += sm[OFF_SS + i];
    float invS = __frcp_rn(S);

    float p0 = 0.f, p1 = 0.f;
    for (int d = tid; d < D; d += NT) {
        float rc = 0.f, a0 = 0.f, a1 = 0.f;
#pragma unroll
        for (int i = 0; i < NW; i++) {
            rc += sm[OFF_BUFC + i * D + d];
            a0 += sm[OFF_BA0 + i * D + d];
            a1 += sm[OFF_BA1 + i * D + d];
        }
        out[BD + (size_t)b * D + d] = rc * invS;
        float wca = __ldg(&W_ca[d]);
        p0 = fmaf(tanha(sm[OFF_C0 + d] + a0), wca, p0);
        p1 = fmaf(tanha(sm[OFF_C1 + d] + a1), wca, p1);
    }
#pragma unroll
    for (int off = 16; off; off >>= 1) {
        p0 += __shfl_xor_sync(0xffffffffu, p0, off);
        p1 += __shfl_xor_sync(0xffffffffu, p1, off);
    }
    if (lane == 0) { sm[OFF_R0 + w] = p0; sm[OFF_R1 + w] = p1; }
    __syncthreads();

    float L0 = 0.f, L1 = 0.f;
#pragma unroll
    for (int i = 0; i < NW; i++) { L0 += sm[OFF_R0 + i]; L1 += sm[OFF_R1 + i]; }
    float mm = fmaxf(L0, L1);
    float e0 = __expf(L0 - mm), e1 = __expf(L1 - mm);
    float inv2 = __frcp_rn(e0 + e1);
    float w0 = e0 * inv2, w1 = e1 * inv2;
    if (tid == 0) {
        out[2 * BD + 2 * b + 0] = w0;
        out[2 * BD + 2 * b + 1] = w1;
    }
    for (int d = tid; d < D; d += NT)
        out[(size_t)b * D + d] = fmaf(sm[OFF_C0 + d], w0, sm[OFF_C1 + d] * w1);
}

extern "C" void kernel_launch(void* const* d_in, const int* in_sizes, int n_in,
                              void* d_out, int out_size)
{
    const float* text        = (const float*)d_in[0];
    const float* img         = (const float*)d_in[1];
    const float* comment     = (const float*)d_in[2];
    const int*   comment_num = (const int*)d_in[3];
    const float* cow         = (const float*)d_in[4];
    const float* W_ca        = (const float*)d_in[5];
    // d_in[6] = b_ca: cancels in softmax
    const float* W_co        = (const float*)d_in[7];
    // d_in[8] = b_co: cancels in softmax
    float* out = (float*)d_out;

    cudaFuncSetAttribute(fuse_kernel, cudaFuncAttributeMaxDynamicSharedMemorySize, SMEM_BYTES);

    dim3 g1(D / 128, (2 * B) / 128);   // (4, 32)
    gemm_cw_tf32<<<g1, 256>>>(text, img, cow);
    fuse_kernel<<<B, NT, SMEM_BYTES>>>(text, img, comment, comment_num, W_ca, W_co, out);
}

// round 8
// speedup vs baseline: 1.7611x; 1.0943x over previous
#include <cuda_runtime.h>
#include <math.h>
#include <stdint.h>

#define B 2048
#define N 128
#define D 512
#define BD (B * D)
#define NW 8             // warps per CTA in fuse kernel
#define NT (NW * 32)     // 256 threads

// 8 MB scratch for cw = content @ cow, rows interleaved: row 2b = text[b]@cow, 2b+1 = img[b]@cow
__device__ float g_cw[2 * B * D];

__device__ __forceinline__ float tanha(float x) {
    float y;
    asm("tanh.approx.f32 %0, %1;" : "=f"(y) : "f"(x));
    return y;
}
__device__ __forceinline__ float ex2(float x) {
    float y;
    asm("ex2.approx.f32 %0, %1;" : "=f"(y) : "f"(x));
    return y;
}
__device__ __forceinline__ uint32_t f2tf32(float x) {
    uint32_t r;
    asm("cvt.rna.tf32.f32 %0, %1;" : "=r"(r) : "f"(x));
    return r;
}
__device__ __forceinline__ void mma_tf32(float c[4], const uint32_t a[4], const uint32_t b[2]) {
    asm volatile(
        "mma.sync.aligned.m16n8k8.row.col.f32.tf32.tf32.f32 "
        "{%0,%1,%2,%3}, {%4,%5,%6,%7}, {%8,%9}, {%0,%1,%2,%3};"
        : "+f"(c[0]), "+f"(c[1]), "+f"(c[2]), "+f"(c[3])
        : "r"(a[0]), "r"(a[1]), "r"(a[2]), "r"(a[3]), "r"(b[0]), "r"(b[1]));
}
__device__ __forceinline__ void cp_async16(void* smem_dst, const void* gmem_src) {
    uint32_t s = (uint32_t)__cvta_generic_to_shared(smem_dst);
    asm volatile("cp.async.ca.shared.global [%0], [%1], 16;" :: "r"(s), "l"(gmem_src));
}
__device__ __forceinline__ void cp_commit() {
    asm volatile("cp.async.commit_group;");
}

// ---------------------------------------------------------------------------
// Kernel 1: cw[4096,512] = A[4096,512] @ cow[512,512] via tf32x3 mma.sync.
// Tile M=64 N=128 K=32; grid 256 CTAs; 2-stage cp.async double buffering.
// Warp grid 2(m) x 4(n): each warp 32x32 = 2 m16-frags x 4 n8-frags.
// ---------------------------------------------------------------------------
#define GM_KT 32
#define AST 36     // A row stride (floats): [m][k] padded
#define WST 132    // W row stride (floats): [k][n] padded
#define A_STAGE (64 * AST)
#define W_STAGE (GM_KT * WST)
#define GEMM_SMEM_BYTES ((2 * A_STAGE + 2 * W_STAGE) * 4)

__global__ __launch_bounds__(256) void gemm_cw_tf32(
    const float* __restrict__ text,
    const float* __restrict__ img,
    const float* __restrict__ cow)
{
    extern __shared__ float gsm[];
    float* As = gsm;                     // 2 stages of [64][AST]
    float* Ws = gsm + 2 * A_STAGE;       // 2 stages of [GM_KT][WST]

    const int t = threadIdx.x;
    const int wid = t >> 5;
    const int lane = t & 31;
    const int warp_m = (wid & 1) * 32;
    const int warp_n = (wid >> 1) * 32;
    const int brow = blockIdx.y * 64;
    const int bcol = blockIdx.x * 128;
    const int g  = lane >> 2;   // 0..7
    const int tg = lane & 3;    // 0..3

    float c[2][4][4];
#pragma unroll
    for (int mi = 0; mi < 2; mi++)
#pragma unroll
        for (int ni = 0; ni < 4; ni++)
#pragma unroll
            for (int j = 0; j < 4; j++) c[mi][ni][j] = 0.f;

    // stage loader: A (64 x 32 floats, [m][k]) + W (32 x 128 floats, [k][n])
    auto load_stage = [&](int st, int k0) {
#pragma unroll
        for (int s = 0; s < 2; s++) {               // A: 512 x 16B / 256 thr
            int f = t + 256 * s;
            int r = f >> 3;
            int kk = (f & 7) * 4;
            int gr = brow + r;
            const float* src = ((gr & 1) ? img : text) + (size_t)(gr >> 1) * D + k0 + kk;
            cp_async16(&As[st * A_STAGE + r * AST + kk], src);
        }
#pragma unroll
        for (int s = 0; s < 4; s++) {               // W: 1024 x 16B / 256 thr
            int f = t + 256 * s;
            int kk = f >> 5;
            int n = (f & 31) * 4;
            const float* src = cow + (size_t)(k0 + kk) * D + bcol + n;
            cp_async16(&Ws[st * W_STAGE + kk * WST + n], src);
        }
    };

    const int NKT = D / GM_KT;   // 16
    load_stage(0, 0);
    cp_commit();

    for (int kt = 0; kt < NKT; kt++) {
        if (kt + 1 < NKT) {
            load_stage((kt + 1) & 1, (kt + 1) * GM_KT);
            cp_commit();
            asm volatile("cp.async.wait_group 1;");
        } else {
            asm volatile("cp.async.wait_group 0;");
        }
        __syncthreads();

        const float* Ab = As + (kt & 1) * A_STAGE;
        const float* Wb = Ws + (kt & 1) * W_STAGE;

#pragma unroll
        for (int k8 = 0; k8 < GM_KT; k8 += 8) {
            uint32_t ahi[2][4], alo[2][4];
#pragma unroll
            for (int mi = 0; mi < 2; mi++) {
                int r0 = warp_m + mi * 16;
                float av[4];
                av[0] = Ab[(r0 + g)     * AST + k8 + tg];
                av[1] = Ab[(r0 + 8 + g) * AST + k8 + tg];
                av[2] = Ab[(r0 + g)     * AST + k8 + tg + 4];
                av[3] = Ab[(r0 + 8 + g) * AST + k8 + tg + 4];
#pragma unroll
                for (int j = 0; j < 4; j++) {
                    uint32_t h = f2tf32(av[j]);
                    ahi[mi][j] = h;
                    alo[mi][j] = __float_as_uint(av[j] - __uint_as_float(h));
                }
            }
            uint32_t bhi[4][2], blo[4][2];
#pragma unroll
            for (int ni = 0; ni < 4; ni++) {
                int n0 = warp_n + ni * 8;
                float bv[2];
                bv[0] = Wb[(k8 + tg)     * WST + n0 + g];
                bv[1] = Wb[(k8 + tg + 4) * WST + n0 + g];
#pragma unroll
                for (int j = 0; j < 2; j++) {
                    uint32_t h = f2tf32(bv[j]);
                    bhi[ni][j] = h;
                    blo[ni][j] = __float_as_uint(bv[j] - __uint_as_float(h));
                }
            }
#pragma unroll
            for (int mi = 0; mi < 2; mi++)
#pragma unroll
                for (int ni = 0; ni < 4; ni++) {
                    mma_tf32(c[mi][ni], alo[mi], bhi[ni]);
                    mma_tf32(c[mi][ni], ahi[mi], blo[ni]);
                    mma_tf32(c[mi][ni], ahi[mi], bhi[ni]);
                }
        }
        __syncthreads();   // protect buffer reuse by next iteration's loads
    }

    // Store C: c[mi][ni] = {(row g, col 2tg), (g, 2tg+1), (g+8, 2tg), (g+8, 2tg+1)}
#pragma unroll
    for (int mi = 0; mi < 2; mi++)
#pragma unroll
        for (int ni = 0; ni < 4; ni++) {
            int row = brow + warp_m + mi * 16 + g;
            int col = bcol + warp_n + ni * 8 + 2 * tg;
            float2 v0 = make_float2(c[mi][ni][0], c[mi][ni][1]);
            float2 v1 = make_float2(c[mi][ni][2], c[mi][ni][3]);
            *reinterpret_cast<float2*>(&g_cw[(size_t)row * D + col]) = v0;
            *reinterpret_cast<float2*>(&g_cw[(size_t)(row + 8) * D + col]) = v1;
        }
}

// Dynamic SMEM layout for fuse kernel (floats)
#define OFF_CW0  0
#define OFF_CW1  (OFF_CW0 + D)
#define OFF_C0   (OFF_CW1 + D)
#define OFF_C1   (OFF_C0 + D)
#define OFF_BUFC (OFF_C1 + D)              // NW*D : per-warp aC
#define OFF_BA0  (OFF_BUFC + NW * D)       // NW*D : per-warp aA0
#define OFF_BA1  (OFF_BA0 + NW * D)        // NW*D : per-warp aA1
#define OFF_SS   (OFF_BA1 + NW * D)        // NW
#define OFF_R0   (OFF_SS + NW)             // NW
#define OFF_R1   (OFF_R0 + NW)             // NW
#define SMEM_FLOATS (OFF_R1 + NW)
#define SMEM_BYTES  (SMEM_FLOATS * 4)

// ---------------------------------------------------------------------------
// Kernel 2: one CTA (8 warps, 256 thr, <=128 regs, 2 CTAs/SM) per sample.
// ---------------------------------------------------------------------------
__global__ __launch_bounds__(NT, 2) void fuse_kernel(
    const float* __restrict__ text,
    const float* __restrict__ img,
    const float* __restrict__ comment,
    const int*   __restrict__ comment_num,
    const float* __restrict__ W_ca,
    const float* __restrict__ W_co,
    float* __restrict__ out)
{
    extern __shared__ float sm[];
    const int b = blockIdx.x;
    const int tid = threadIdx.x;
    const int w = tid >> 5;
    const int lane = tid & 31;

    for (int d = tid; d < D; d += NT) {
        sm[OFF_CW0 + d] = g_cw[(size_t)(2 * b) * D + d];
        sm[OFF_CW1 + d] = g_cw[(size_t)(2 * b + 1) * D + d];
        sm[OFF_C0 + d]  = text[(size_t)b * D + d];
        sm[OFF_C1 + d]  = img[(size_t)b * D + d];
    }
    __syncthreads();

    const float LOG2E = 1.4426950408889634f;
    float4 wr[4];
#pragma unroll
    for (int j = 0; j < 4; j++) {
        float4 wv = __ldg(&reinterpret_cast<const float4*>(W_co)[lane + 32 * j]);
        wr[j] = make_float4(wv.x * LOG2E, wv.y * LOG2E, wv.z * LOG2E, wv.w * LOG2E);
    }

    const int num = comment_num[b];
    const float4* zbase = reinterpret_cast<const float4*>(comment + (size_t)b * N * D);

    float4 aA0[4], aA1[4], aC[4];
#pragma unroll
    for (int j = 0; j < 4; j++) {
        aA0[j] = make_float4(0.f, 0.f, 0.f, 0.f);
        aA1[j] = make_float4(0.f, 0.f, 0.f, 0.f);
        aC[j]  = make_float4(0.f, 0.f, 0.f, 0.f);
    }
    float ssum = 0.f;

    float4 zb[4];
    if (w < num) {
        const float4* zr = zbase + (size_t)w * (D / 4);
#pragma unroll
        for (int j = 0; j < 4; j++) zb[j] = __ldg(&zr[lane + 32 * j]);
    }

    for (int n = w; n < num; n += NW) {
        float4 zc[4];
#pragma unroll
        for (int j = 0; j < 4; j++) zc[j] = zb[j];

        int nn = n + NW;
        if (nn < num) {
            const float4* zr = zbase + (size_t)nn * (D / 4);
#pragma unroll
            for (int j = 0; j < 4; j++) zb[j] = __ldg(&zr[lane + 32 * j]);
        }

        float d0a = 0.f, d0b = 0.f, d1a = 0.f, d1b = 0.f;
#pragma unroll
        for (int j = 0; j < 2; j++) {
            int q0 = lane + 32 * j;
            int q1 = lane + 32 * (j + 2);
            float4 a0 = reinterpret_cast<const float4*>(sm + OFF_CW0)[q0];
            float4 a1 = reinterpret_cast<const float4*>(sm + OFF_CW0)[q1];
            float4 c0 = reinterpret_cast<const float4*>(sm + OFF_CW1)[q0];
            float4 c1 = reinterpret_cast<const float4*>(sm + OFF_CW1)[q1];
            d0a = fmaf(zc[j].x, a0.x, fmaf(zc[j].y, a0.y, fmaf(zc[j].z, a0.z, fmaf(zc[j].w, a0.w, d0a))));
            d0b = fmaf(zc[j+2].x, a1.x, fmaf(zc[j+2].y, a1.y, fmaf(zc[j+2].z, a1.z, fmaf(zc[j+2].w, a1.w, d0b))));
            d1a = fmaf(zc[j].x, c0.x, fmaf(zc[j].y, c0.y, fmaf(zc[j].z, c0.z, fmaf(zc[j].w, c0.w, d1a))));
            d1b = fmaf(zc[j+2].x, c1.x, fmaf(zc[j+2].y, c1.y, fmaf(zc[j+2].z, c1.z, fmaf(zc[j+2].w, c1.w, d1b))));
        }
        float d0 = d0a + d0b, d1 = d1a + d1b;
#pragma unroll
        for (int off = 16; off; off >>= 1) {
            d0 += __shfl_xor_sync(0xffffffffu, d0, off);
            d1 += __shfl_xor_sync(0xffffffffu, d1, off);
        }
        float t0 = tanha(d0);
        float t1 = tanha(d1);

        float lpa = 0.f, lpb = 0.f;
#pragma unroll
        for (int j = 0; j < 4; j++) {
            int q = lane + 32 * j;
            float4 c0 = reinterpret_cast<const float4*>(sm + OFF_C0)[q];
            float4 c1 = reinterpret_cast<const float4*>(sm + OFF_C1)[q];
            float zt;
            zt = tanha(fmaf(t0, c0.x, fmaf(t1, c1.x, zc[j].x))); lpa = fmaf(zt, wr[j].x, lpa);
            zt = tanha(fmaf(t0, c0.y, fmaf(t1, c1.y, zc[j].y))); lpb = fmaf(zt, wr[j].y, lpb);
            zt = tanha(fmaf(t0, c0.z, fmaf(t1, c1.z, zc[j].z))); lpa = fmaf(zt, wr[j].z, lpa);
            zt = tanha(fmaf(t0, c0.w, fmaf(t1, c1.w, zc[j].w))); lpb = fmaf(zt, wr[j].w, lpb);
            aA0[j].x = fmaf(t0, zc[j].x, aA0[j].x);
            aA0[j].y = fmaf(t0, zc[j].y, aA0[j].y);
            aA0[j].z = fmaf(t0, zc[j].z, aA0[j].z);
            aA0[j].w = fmaf(t0, zc[j].w, aA0[j].w);
            aA1[j].x = fmaf(t1, zc[j].x, aA1[j].x);
            aA1[j].y = fmaf(t1, zc[j].y, aA1[j].y);
            aA1[j].z = fmaf(t1, zc[j].z, aA1[j].z);
            aA1[j].w = fmaf(t1, zc[j].w, aA1[j].w);
        }
        float lp = lpa + lpb;
#pragma unroll
        for (int off = 16; off; off >>= 1)
            lp += __shfl_xor_sync(0xffffffffu, lp, off);
        float e = ex2(lp);
        ssum += e;
#pragma unroll
        for (int j = 0; j < 4; j++) {
            aC[j].x = fmaf(e, zc[j].x, aC[j].x);
            aC[j].y = fmaf(e, zc[j].y, aC[j].y);
            aC[j].z = fmaf(e, zc[j].z, aC[j].z);
            aC[j].w = fmaf(e, zc[j].w, aC[j].w);
        }
    }

    if (lane == 0) sm[OFF_SS + w] = ssum;
#pragma unroll
    for (int j = 0; j < 4; j++) {
        int q = lane + 32 * j;
        reinterpret_cast<float4*>(sm + OFF_BUFC + w * D)[q] = aC[j];
        reinterpret_cast<float4*>(sm + OFF_BA0 + w * D)[q]  = aA0[j];
        reinterpret_cast<float4*>(sm + OFF_BA1 + w * D)[q]  = aA1[j];
    }
    __syncthreads();

    float S = 0.f;
#pragma unroll
    for (int i = 0; i < NW; i++) S += sm[OFF_SS + i];
    float invS = __frcp_rn(S);

    float p0 = 0.f, p1 = 0.f;
    for (int d = tid; d < D; d += NT) {
        float rc = 0.f, a0 = 0.f, a1 = 0.f;
#pragma unroll
        for (int i = 0; i < NW; i++) {
            rc += sm[OFF_BUFC + i * D + d];
            a0 += sm[OFF_BA0 + i * D + d];
            a1 += sm[OFF_BA1 + i * D + d];
        }
        out[BD + (size_t)b * D + d] = rc * invS;
        float wca = __ldg(&W_ca[d]);
        p0 = fmaf(tanha(sm[OFF_C0 + d] + a0), wca, p0);
        p1 = fmaf(tanha(sm[OFF_C1 + d] + a1), wca, p1);
    }
#pragma unroll
    for (int off = 16; off; off >>= 1) {
        p0 += __shfl_xor_sync(0xffffffffu, p0, off);
        p1 += __shfl_xor_sync(0xffffffffu, p1, off);
    }
    if (lane == 0) { sm[OFF_R0 + w] = p0; sm[OFF_R1 + w] = p1; }
    __syncthreads();

    float L0 = 0.f, L1 = 0.f;
#pragma unroll
    for (int i = 0; i < NW; i++) { L0 += sm[OFF_R0 + i]; L1 += sm[OFF_R1 + i]; }
    float mm = fmaxf(L0, L1);
    float e0 = __expf(L0 - mm), e1 = __expf(L1 - mm);
    float inv2 = __frcp_rn(e0 + e1);
    float w0 = e0 * inv2, w1 = e1 * inv2;
    if (tid == 0) {
        out[2 * BD + 2 * b + 0] = w0;
        out[2 * BD + 2 * b + 1] = w1;
    }
    for (int d = tid; d < D; d += NT)
        out[(size_t)b * D + d] = fmaf(sm[OFF_C0 + d], w0, sm[OFF_C1 + d] * w1);
}

extern "C" void kernel_launch(void* const* d_in, const int* in_sizes, int n_in,
                              void* d_out, int out_size)
{
    const float* text        = (const float*)d_in[0];
    const float* img         = (const float*)d_in[1];
    const float* comment     = (const float*)d_in[2];
    const int*   comment_num = (const int*)d_in[3];
    const float* cow         = (const float*)d_in[4];
    const float* W_ca        = (const float*)d_in[5];
    // d_in[6] = b_ca: cancels in softmax
    const float* W_co        = (const float*)d_in[7];
    // d_in[8] = b_co: cancels in softmax
    float* out = (float*)d_out;

    cudaFuncSetAttribute(gemm_cw_tf32, cudaFuncAttributeMaxDynamicSharedMemorySize, GEMM_SMEM_BYTES);
    cudaFuncSetAttribute(fuse_kernel, cudaFuncAttributeMaxDynamicSharedMemorySize, SMEM_BYTES);

    dim3 g1(D / 128, (2 * B) / 64);   // (4, 64) = 256 CTAs
    gemm_cw_tf32<<<g1, 256, GEMM_SMEM_BYTES>>>(text, img, cow);
    fuse_kernel<<<B, NT, SMEM_BYTES>>>(text, img, comment, comment_num, W_ca, W_co, out);
}